// round 4
// baseline (speedup 1.0000x reference)
#include <cuda_runtime.h>

// Controlled-SX on qutrits (dim=3, 16 qudits), ctrl=2, obj=5.
//   d2!=1          : out[i] = in[i]
//   d2==1, d5==0   : out[i] = in[i + 3^10]
//   d2==1, d5==1   : out[i] = in[i - 3^10]
//   d2==1, d5==2   : out[i] = 0
// 1 thread = 1 oct (8 consecutive i = 2 float4 quads per plane).
// Digits change only at multiples of S5 = 3^10; octs straddling a boundary
// (1/7381) take the scalar path.
// out_im = d_out + n with n odd -> 4B-aligned only: scalar stores for im.

static constexpr int S5 = 59049;    // 3^10
static constexpr int S2 = 1594323;  // 3^13 = 27 * S5

__device__ __forceinline__ void scalar_one(const float* __restrict__ in_re,
                                           const float* __restrict__ in_im,
                                           float* __restrict__ out_re,
                                           float* __restrict__ out_im,
                                           int idx)
{
    int q5 = idx / S5;
    int d5 = q5 % 3;
    int d2 = (q5 / 27) % 3;
    float vr, vi;
    if (d2 != 1) {
        vr = __ldg(in_re + idx);
        vi = __ldg(in_im + idx);
    } else if (d5 == 0) {
        vr = __ldg(in_re + idx + S5);
        vi = __ldg(in_im + idx + S5);
    } else if (d5 == 1) {
        vr = __ldg(in_re + idx - S5);
        vi = __ldg(in_im + idx - S5);
    } else {
        vr = 0.0f; vi = 0.0f;
    }
    out_re[idx] = vr;
    out_im[idx] = vi;
}

__global__ void __launch_bounds__(256)
sx_apply_v8(const float* __restrict__ in_re,
            const float* __restrict__ in_im,
            float* __restrict__ out_re,
            float* __restrict__ out_im,   // 4B-aligned only: scalar stores
            int n, int noct)
{
    int t = blockIdx.x * blockDim.x + threadIdx.x;
    if (t >= noct) return;
    int i = t << 3;                   // 8 elements per thread

    int q5 = i / S5;                  // one magic-mul divide per 8 elements
    int r5 = i - q5 * S5;
    int d5 = q5 % 3;
    int d2 = (q5 / 27) % 3;

    bool fast = (i + 8 <= n) && (r5 + 8 <= S5);

    if (fast) {
        const float4* in_re4  = reinterpret_cast<const float4*>(in_re);
        const float4* in_im4  = reinterpret_cast<const float4*>(in_im);
        float4*       out_re4 = reinterpret_cast<float4*>(out_re);
        int q = t << 1;               // quad index

        float4 vr0, vr1, vi0, vi1;
        if (d2 != 1) {
            // 4 front-batched LDG.128 -> 2KB in flight per warp per plane-pair
            vr0 = __ldg(in_re4 + q);
            vr1 = __ldg(in_re4 + q + 1);
            vi0 = __ldg(in_im4 + q);
            vi1 = __ldg(in_im4 + q + 1);
        } else if (d5 == 2) {
            vr0 = make_float4(0.f, 0.f, 0.f, 0.f);
            vr1 = vr0; vi0 = vr0; vi1 = vr0;
        } else {
            int s = (d5 == 0) ? (i + S5) : (i - S5);  // odd offset: scalar gather
            float r[8], m[8];
            #pragma unroll
            for (int j = 0; j < 8; j++) r[j] = __ldg(in_re + s + j);
            #pragma unroll
            for (int j = 0; j < 8; j++) m[j] = __ldg(in_im + s + j);
            vr0 = make_float4(r[0], r[1], r[2], r[3]);
            vr1 = make_float4(r[4], r[5], r[6], r[7]);
            vi0 = make_float4(m[0], m[1], m[2], m[3]);
            vi1 = make_float4(m[4], m[5], m[6], m[7]);
        }
        out_re4[q]     = vr0;         // STG.128 x2 (aligned)
        out_re4[q + 1] = vr1;
        out_im[i + 0] = vi0.x;        // STG.32 x8 (out_im only 4B-aligned)
        out_im[i + 1] = vi0.y;
        out_im[i + 2] = vi0.z;
        out_im[i + 3] = vi0.w;
        out_im[i + 4] = vi1.x;
        out_im[i + 5] = vi1.y;
        out_im[i + 6] = vi1.z;
        out_im[i + 7] = vi1.w;
    } else {
        #pragma unroll
        for (int j = 0; j < 8; j++) {
            int idx = i + j;
            if (idx < n)
                scalar_one(in_re, in_im, out_re, out_im, idx);
        }
    }
}

extern "C" void kernel_launch(void* const* d_in, const int* in_sizes, int n_in,
                              void* d_out, int out_size)
{
    const float* in_re = (const float*)d_in[0];
    const float* in_im = (const float*)d_in[1];
    const int n = in_sizes[0];          // 3^16 = 43,046,721 (odd)

    float* out_re = (float*)d_out;
    float* out_im = (float*)d_out + n;  // 4B-aligned only

    const int noct = (n + 7) >> 3;
    const int threads = 256;
    const int blocks = (noct + threads - 1) / threads;
    sx_apply_v8<<<blocks, threads>>>(in_re, in_im, out_re, out_im, n, noct);
}

// round 5
// speedup vs baseline: 1.9452x; 1.9452x over previous
#include <cuda_runtime.h>

// Controlled-SX on qutrits (dim=3, 16 qudits), ctrl=2, obj=5.
//   d2!=1          : out[i] = in[i]
//   d2==1, d5==0   : out[i] = in[i + 3^10]
//   d2==1, d5==1   : out[i] = in[i - 3^10]
//   d2==1, d5==2   : out[i] = 0
// 2 quads per thread, WARP-STRIDED (+blockDim) so every LDG.128/STG.128 is
// fully coalesced (lane-adjacent addresses 16B apart). R4 lesson: consecutive
// quads per thread half-fill sectors and tank L1 throughput.
// out_im = d_out + n with n odd -> 4B-aligned only: scalar stores for im.

static constexpr int S5 = 59049;    // 3^10
static constexpr int S2 = 1594323;  // 3^13 = 27 * S5

__device__ __forceinline__ void scalar_one(const float* __restrict__ in_re,
                                           const float* __restrict__ in_im,
                                           float* __restrict__ out_re,
                                           float* __restrict__ out_im,
                                           int idx)
{
    int q5 = idx / S5;
    int d5 = q5 % 3;
    int d2 = (q5 / 27) % 3;
    float vr, vi;
    if (d2 != 1) {
        vr = __ldg(in_re + idx);
        vi = __ldg(in_im + idx);
    } else if (d5 == 0) {
        vr = __ldg(in_re + idx + S5);
        vi = __ldg(in_im + idx + S5);
    } else if (d5 == 1) {
        vr = __ldg(in_re + idx - S5);
        vi = __ldg(in_im + idx - S5);
    } else {
        vr = 0.0f; vi = 0.0f;
    }
    out_re[idx] = vr;
    out_im[idx] = vi;
}

__device__ __forceinline__ void do_quad(const float* __restrict__ in_re,
                                        const float* __restrict__ in_im,
                                        float* __restrict__ out_re,
                                        float* __restrict__ out_im,
                                        int n, int q)
{
    int i = q << 2;

    int q5 = i / S5;                 // magic-mul divide
    int r5 = i - q5 * S5;
    int d5 = q5 % 3;
    int d2 = (q5 / 27) % 3;

    bool fast = (i + 4 <= n) && (r5 + 4 <= S5);

    if (fast) {
        const float4* in_re4  = reinterpret_cast<const float4*>(in_re);
        const float4* in_im4  = reinterpret_cast<const float4*>(in_im);
        float4*       out_re4 = reinterpret_cast<float4*>(out_re);

        float4 vr, vi;
        if (d2 != 1) {
            vr = __ldg(in_re4 + q);          // LDG.128, fully coalesced
            vi = __ldg(in_im4 + q);
        } else if (d5 == 2) {
            vr = make_float4(0.f, 0.f, 0.f, 0.f);
            vi = vr;
        } else {
            int s = (d5 == 0) ? (i + S5) : (i - S5);  // odd offset: scalar gather
            vr.x = __ldg(in_re + s + 0);
            vr.y = __ldg(in_re + s + 1);
            vr.z = __ldg(in_re + s + 2);
            vr.w = __ldg(in_re + s + 3);
            vi.x = __ldg(in_im + s + 0);
            vi.y = __ldg(in_im + s + 1);
            vi.z = __ldg(in_im + s + 2);
            vi.w = __ldg(in_im + s + 3);
        }
        out_re4[q] = vr;                     // STG.128 (aligned)
        out_im[i + 0] = vi.x;                // STG.32 x4 (out_im 4B-aligned only)
        out_im[i + 1] = vi.y;
        out_im[i + 2] = vi.z;
        out_im[i + 3] = vi.w;
    } else {
        #pragma unroll
        for (int j = 0; j < 4; j++) {
            int idx = i + j;
            if (idx < n)
                scalar_one(in_re, in_im, out_re, out_im, idx);
        }
    }
}

__global__ void __launch_bounds__(256)
sx_apply_v4x2(const float* __restrict__ in_re,
              const float* __restrict__ in_im,
              float* __restrict__ out_re,
              float* __restrict__ out_im,
              int n, int nq)
{
    // Block owns 2*blockDim contiguous quads; thread takes tid and tid+blockDim.
    int q0 = blockIdx.x * (blockDim.x * 2) + threadIdx.x;
    int q1 = q0 + blockDim.x;

    if (q0 < nq) do_quad(in_re, in_im, out_re, out_im, n, q0);
    if (q1 < nq) do_quad(in_re, in_im, out_re, out_im, n, q1);
}

extern "C" void kernel_launch(void* const* d_in, const int* in_sizes, int n_in,
                              void* d_out, int out_size)
{
    const float* in_re = (const float*)d_in[0];
    const float* in_im = (const float*)d_in[1];
    const int n = in_sizes[0];          // 3^16 = 43,046,721 (odd)

    float* out_re = (float*)d_out;
    float* out_im = (float*)d_out + n;  // 4B-aligned only

    const int nq = (n + 3) >> 2;
    const int threads = 256;
    const int quads_per_block = threads * 2;
    const int blocks = (nq + quads_per_block - 1) / quads_per_block;
    sx_apply_v4x2<<<blocks, threads>>>(in_re, in_im, out_re, out_im, n, nq);
}